// round 1
// baseline (speedup 1.0000x reference)
#include <cuda_runtime.h>

// Double-pendulum Hamiltonian dynamics, closed form.
// Constants: M1=M2=L1=L2=1, G=9.81.
// State tp = (th1, th2, p1, p2). Output (dq1, dq2, dp1, dp2).
//
// Mass matrix M = [[2, c],[c, 1]], c = cos(th1 - th2), det D = 2 - c^2.
// Kinetic (in momenta): K = (p1^2 - 2 c p1 p2 + 2 p2^2) / (2D)
// dq = dK/dp = M^{-1} p
// dK/dc = (c*N - D*p1*p2)/D^2 with N = p1^2 - 2 c p1 p2 + 2 p2^2
// dp1 = -dH/dth1 =  s*dK/dc - 2*G*sin(th1)
// dp2 = -dH/dth2 = -s*dK/dc -   G*sin(th2)
// where s = sin(th1 - th2).

#define GCONST 9.81f

__global__ void pendelum2dof_kernel(const float4* __restrict__ y,
                                    float4* __restrict__ out,
                                    int n) {
    int i = blockIdx.x * blockDim.x + threadIdx.x;
    if (i >= n) return;

    float4 st = y[i];
    float th1 = st.x, th2 = st.y, p1 = st.z, p2 = st.w;

    float d = th1 - th2;
    float s, c;
    sincosf(d, &s, &c);

    float D    = 2.0f - c * c;
    float invD = 1.0f / D;

    float dq1 = (p1 - c * p2) * invD;
    float dq2 = (2.0f * p2 - c * p1) * invD;

    float p1p2 = p1 * p2;
    float N    = p1 * p1 - 2.0f * c * p1p2 + 2.0f * p2 * p2;
    float dKdc = (c * N - D * p1p2) * invD * invD;

    float dp1 = s * dKdc - 2.0f * GCONST * sinf(th1);
    float dp2 = -s * dKdc - GCONST * sinf(th2);

    out[i] = make_float4(dq1, dq2, dp1, dp2);
}

extern "C" void kernel_launch(void* const* d_in, const int* in_sizes, int n_in,
                              void* d_out, int out_size) {
    // d_in[0] = t (1 float, unused ODE time), d_in[1] = y (B*4 floats)
    const float4* y = (const float4*)d_in[1];
    float4* out = (float4*)d_out;
    int n = in_sizes[1] / 4;  // number of states (float4 elements)

    const int TPB = 256;
    int blocks = (n + TPB - 1) / TPB;
    pendelum2dof_kernel<<<blocks, TPB>>>(y, out, n);
}

// round 2
// speedup vs baseline: 1.0435x; 1.0435x over previous
#include <cuda_runtime.h>

// Double-pendulum Hamiltonian dynamics, closed form (M1=M2=L1=L2=1, G=9.81).
// State tp = (th1, th2, p1, p2) -> (dq1, dq2, dp1, dp2).
//
// c = cos(th1-th2), s = sin(th1-th2), D = 2 - c^2
// dq1 = (p1 - c p2)/D ; dq2 = (2 p2 - c p1)/D
// N = p1^2 - 2 c p1 p2 + 2 p2^2 ; dK/dc = (c N - D p1 p2)/D^2
// dp1 =  s dK/dc - 2 G sin(th1) ; dp2 = -s dK/dc - G sin(th2)
//
// Latency-optimized: 2 front-batched float4 loads per thread (MLP=2),
// MUFU fast-math transcendentals (__sincosf/__sinf) to shorten the
// serial dependency chain.

#define GCONST 9.81f
#define ELEMS_PER_THREAD 2

__device__ __forceinline__ float4 dyn(float4 st) {
    float th1 = st.x, th2 = st.y, p1 = st.z, p2 = st.w;

    float s, c;
    __sincosf(th1 - th2, &s, &c);

    float D    = 2.0f - c * c;
    float invD = __frcp_rn(D);

    float dq1 = (p1 - c * p2) * invD;
    float dq2 = (2.0f * p2 - c * p1) * invD;

    float p1p2 = p1 * p2;
    float N    = p1 * p1 - 2.0f * c * p1p2 + 2.0f * p2 * p2;
    float dKdc = (c * N - D * p1p2) * invD * invD;

    float sd = s * dKdc;
    float dp1 =  sd - 2.0f * GCONST * __sinf(th1);
    float dp2 = -sd -        GCONST * __sinf(th2);

    return make_float4(dq1, dq2, dp1, dp2);
}

__global__ void __launch_bounds__(256)
pendelum2dof_kernel(const float4* __restrict__ y,
                    float4* __restrict__ out,
                    int n) {
    int base = blockIdx.x * (blockDim.x * ELEMS_PER_THREAD) + threadIdx.x;

    // Front-batch both loads (independent, warp-contiguous) for MLP=2.
    float4 a, b;
    int i0 = base;
    int i1 = base + blockDim.x;
    bool v0 = i0 < n;
    bool v1 = i1 < n;
    if (v0) a = y[i0];
    if (v1) b = y[i1];

    if (v0) out[i0] = dyn(a);
    if (v1) out[i1] = dyn(b);
}

extern "C" void kernel_launch(void* const* d_in, const int* in_sizes, int n_in,
                              void* d_out, int out_size) {
    const float4* y = (const float4*)d_in[1];
    float4* out = (float4*)d_out;
    int n = in_sizes[1] / 4;  // number of states

    const int TPB = 256;
    int per_block = TPB * ELEMS_PER_THREAD;
    int blocks = (n + per_block - 1) / per_block;
    pendelum2dof_kernel<<<blocks, TPB>>>(y, out, n);
}